// round 15
// baseline (speedup 1.0000x reference)
#include <cuda_runtime.h>
#include <math.h>
#include <cstdint>

#define SEQ   1024
#define BATCH 128
#define EMB   512
#define HID   512
#define ZDIM  2048               // 4*HID
#define NBH   (BATCH * HID)      // 65536
#define NREC  64                 // recurrent CTAs (32 j-tiles x 2 row-groups)
#define NPROD 84                 // xz-producer CTAs
#define NTILE (SEQ * 16)         // xz tiles: 1024 timesteps x 16 n-tiles

// Scratch (allocation-free rule: __device__ globals)
__device__ float    g_xz[(size_t)SEQ * BATCH * ZDIM];   // 1 GiB: x@Wx + b
__device__ unsigned g_arrive[NREC * 8];                 // flag/CTA, 32B stride
__device__ unsigned g_ready[SEQ];                       // xz tiles done per t

// ---------------------------------------------------------------------------
// helpers
// ---------------------------------------------------------------------------
__device__ __forceinline__ unsigned tf32cvt(float x) {
    unsigned u;
    asm("cvt.rna.tf32.f32 %0, %1;" : "=r"(u) : "f"(x));
    return u;
}

__device__ __forceinline__ void mma_tf32(float* c, const unsigned* a, const unsigned* b) {
    asm volatile(
        "mma.sync.aligned.m16n8k8.row.col.f32.tf32.tf32.f32 "
        "{%0,%1,%2,%3}, {%4,%5,%6,%7}, {%8,%9}, {%0,%1,%2,%3};\n"
        : "+f"(c[0]), "+f"(c[1]), "+f"(c[2]), "+f"(c[3])
        : "r"(a[0]), "r"(a[1]), "r"(a[2]), "r"(a[3]), "r"(b[0]), "r"(b[1]));
}

__device__ __forceinline__ float tanh_ap(float x) {
    float y;
    asm("tanh.approx.f32 %0, %1;" : "=f"(y) : "f"(x));
    return y;
}
__device__ __forceinline__ float sigm_ap(float x) {
    return fmaf(tanh_ap(0.5f * x), 0.5f, 0.5f);
}

// acquire load / release store on global flags (no atomic-ALU serialization)
__device__ __forceinline__ unsigned ld_acq(const unsigned* p) {
    unsigned v;
    asm volatile("ld.global.acquire.gpu.u32 %0, [%1];" : "=r"(v) : "l"(p) : "memory");
    return v;
}
__device__ __forceinline__ void st_rel(unsigned* p, unsigned v) {
    asm volatile("st.global.release.gpu.u32 [%0], %1;" :: "l"(p), "r"(v) : "memory");
}

// named barrier: one per K-group (ids 1,2; id 0 left for __syncthreads)
__device__ __forceinline__ void bar_group(int id) {
    asm volatile("bar.sync %0, %1;" :: "r"(id), "r"(128) : "memory");
}

// ---------------------------------------------------------------------------
// reset (graph node 1): flags -> deterministic replays
// ---------------------------------------------------------------------------
__global__ void reset_k() {
    int i = threadIdx.x;
    if (i < SEQ) g_ready[i] = 0;
    if (i < NREC * 8) g_arrive[i] = 0;
}

// ---------------------------------------------------------------------------
// Dynamic smem layout (word offsets), recurrent-CTA view:
//   Bs  [512][72]      : Wh slice, gate-gathered (cached all steps) 147456 B
//   grp0: bufA/bufB [64][68] : 64-k chunks, double buffer           2x17408 B
//   grp1: bufA/bufB [64][68]                                        2x17408 B
//   Zs0 [64][65] overlays grp0 bufA; Zs1 [64][65] overlays grp1 bufA
// Producer-CTA view (overlay at word 0): Asp[128][17] | Bsp[16][136]
//
// Conflict math: Bs stride 72 (72%32=8 -> bank 8*tig+gid: distinct);
//                buf stride 68 (68%32=4 -> bank 4*gid+tig: distinct).
// ---------------------------------------------------------------------------
#define BS_STR  72
#define AB_STR  68
#define AB_WORDS (64 * AB_STR)               // 4352
#define SM_AS   (512 * BS_STR)               // 36864
#define SMEM_WORDS (SM_AS + 4 * AB_WORDS)    // 54272
#define SMEM_BYTES (SMEM_WORDS * 4)          // 217088 <= 232448 max

// ---------------------------------------------------------------------------
// Producer role: compute g_xz tiles (128 rows = one timestep, 128 cols),
// publish g_ready[t]. Verified R3/R5 body, 256 threads.
// ---------------------------------------------------------------------------
__device__ void xz_producer(const float* __restrict__ X,
                            const float* __restrict__ W,
                            const float* __restrict__ bias,
                            unsigned* smw, int pid) {
    unsigned (*As)[17]  = (unsigned(*)[17])smw;
    unsigned (*Bs)[136] = (unsigned(*)[136])(smw + 128 * 17);

    const int tid  = threadIdx.x;
    const int lane = tid & 31;
    const int w    = tid >> 5;
    const int wm = (w & 1) * 64;
    const int wn = (w >> 1) * 32;
    const int gid = lane >> 2;
    const int tig = lane & 3;

    for (int idx = pid; idx < NTILE; idx += NPROD) {
        const int t  = idx >> 4;
        const int bn = idx & 15;

        float acc[4][4][4];
        #pragma unroll
        for (int mt = 0; mt < 4; mt++)
            #pragma unroll
            for (int nt = 0; nt < 4; nt++)
                #pragma unroll
                for (int r = 0; r < 4; r++) acc[mt][nt][r] = 0.0f;

        const float* Ag = X + (size_t)t * 128 * EMB;
        const float* Bg = W + (size_t)bn * 128;

        for (int k0 = 0; k0 < EMB; k0 += 16) {
            #pragma unroll
            for (int i = 0; i < 2; i++) {
                int id2 = tid + i * 256;
                int r = id2 >> 2, c4 = id2 & 3;
                float4 v = *(const float4*)(Ag + (size_t)r * EMB + k0 + c4 * 4);
                As[r][c4 * 4 + 0] = tf32cvt(v.x);
                As[r][c4 * 4 + 1] = tf32cvt(v.y);
                As[r][c4 * 4 + 2] = tf32cvt(v.z);
                As[r][c4 * 4 + 3] = tf32cvt(v.w);
            }
            #pragma unroll
            for (int i = 0; i < 2; i++) {
                int id2 = tid + i * 256;
                int r = id2 >> 5, c4 = id2 & 31;
                float4 v = *(const float4*)(Bg + (size_t)(k0 + r) * ZDIM + c4 * 4);
                Bs[r][c4 * 4 + 0] = tf32cvt(v.x);
                Bs[r][c4 * 4 + 1] = tf32cvt(v.y);
                Bs[r][c4 * 4 + 2] = tf32cvt(v.z);
                Bs[r][c4 * 4 + 3] = tf32cvt(v.w);
            }
            __syncthreads();

            #pragma unroll
            for (int kk = 0; kk < 16; kk += 8) {
                unsigned a[4][4], b[4][2];
                #pragma unroll
                for (int mt = 0; mt < 4; mt++) {
                    int mr = wm + mt * 16;
                    a[mt][0] = As[mr + gid][kk + tig];
                    a[mt][1] = As[mr + gid + 8][kk + tig];
                    a[mt][2] = As[mr + gid][kk + tig + 4];
                    a[mt][3] = As[mr + gid + 8][kk + tig + 4];
                }
                #pragma unroll
                for (int nt = 0; nt < 4; nt++) {
                    int nc = wn + nt * 8;
                    b[nt][0] = Bs[kk + tig][nc + gid];
                    b[nt][1] = Bs[kk + tig + 4][nc + gid];
                }
                #pragma unroll
                for (int mt = 0; mt < 4; mt++)
                    #pragma unroll
                    for (int nt = 0; nt < 4; nt++)
                        mma_tf32(acc[mt][nt], a[mt], b[nt]);
            }
            __syncthreads();
        }

        #pragma unroll
        for (int mt = 0; mt < 4; mt++) {
            #pragma unroll
            for (int nt = 0; nt < 4; nt++) {
                int grow = t * 128 + wm + mt * 16 + gid;
                int gcol = bn * 128 + wn + nt * 8 + 2 * tig;
                float b0 = bias[gcol], b1 = bias[gcol + 1];
                float* p0 = g_xz + (size_t)grow * ZDIM + gcol;
                p0[0] = acc[mt][nt][0] + b0;
                p0[1] = acc[mt][nt][1] + b1;
                float* p1 = g_xz + (size_t)(grow + 8) * ZDIM + gcol;
                p1[0] = acc[mt][nt][2] + b0;
                p1[1] = acc[mt][nt][3] + b1;
            }
        }

        __threadfence();          // producer keeps the conservative fence
        __syncthreads();
        if (tid == 0) atomicAdd(&g_ready[t], 1u);   // 16 contributors: RMW needed
        __syncthreads();
    }
}

// ---------------------------------------------------------------------------
// Persistent kernel: 148 CTAs x 256 threads, one wave.
//   blockIdx.x <  64 : recurrent role (8 warps)
//   blockIdx.x >= 64 : xz-producer role
//
// Recurrent GEMM per step: z[64 x 64] = h_prev[64 x 512] @ WhSlice[512 x 64].
// R14 structure (proven): two decoupled 4-warp pipelines, group g = w>>2
// owns K range [g*256, +256) as 4 chunks of 64 k with its own double buffer
// and named barrier; R12 chunk pipeline inside; atomic-free 2-plane reduce.
//
// NEW (serial-chain trims):
//   - top-of-step xz poll and h-flag poll merged under ONE __syncthreads
//   - g_ready[t+1] prefetched by tid0 right after the top sync (acquire);
//     the blocking poll runs only when the prefetch was incomplete
//   - __threadfence before the arrive removed: bar.sync + st.release.gpu is
//     the standard cumulative release pattern (same as coop-groups grid sync)
// ---------------------------------------------------------------------------
__global__ __launch_bounds__(256, 1) void lstm_persist_k(float* __restrict__ out,
                                                         const float* __restrict__ X,
                                                         const float* __restrict__ W,
                                                         const float* __restrict__ bias) {
    extern __shared__ unsigned smw[];
    const int tid = threadIdx.x;

    if (blockIdx.x >= NREC) {
        xz_producer(X, W, bias, smw, blockIdx.x - NREC);
        return;
    }

    unsigned (*Bs)[BS_STR] = (unsigned(*)[BS_STR])smw;
    float    (*Zs0)[65]    = (float(*)[65])(smw + SM_AS);                // grp0 bufA
    float    (*Zs1)[65]    = (float(*)[65])(smw + SM_AS + 2 * AB_WORDS); // grp1 bufA

    const int cb   = blockIdx.x;
    const int j0   = (cb & 31) * 16;      // hidden-col tile
    const int rg   = cb >> 5;             // row group 0/1
    const int row0 = rg * 64;             // batch-row tile
    const int lane = tid & 31;
    const int w    = tid >> 5;            // 0..7
    const int grp  = w >> 2;              // K-group 0/1 (contiguous 256 k)
    const int wq   = w & 3;               // warp within group
    const int wm   = (wq & 1) * 32;
    const int wn   = (wq >> 1) * 32;
    const int gid  = lane >> 2;
    const int tig  = lane & 3;

    // group-local double buffer
    unsigned (*bufA)[AB_STR] = (unsigned(*)[AB_STR])(smw + SM_AS + grp * 2 * AB_WORDS);
    unsigned (*bufB)[AB_STR] = (unsigned(*)[AB_STR])(smw + SM_AS + grp * 2 * AB_WORDS + AB_WORDS);

    // ---- one-time: cache Wh slice (gate-gathered, tf32) in smem ----
    // Bs[k][n], n = gate*16 + jj  ->  Wh[k][gate*512 + j0 + jj]
    const float* Wh = W + (size_t)EMB * ZDIM;
    #pragma unroll 4
    for (int i = 0; i < 32; i++) {
        int idx  = tid + i * 256;            // 8192 float4s
        int k    = idx >> 4;
        int rem  = idx & 15;
        int gate = rem >> 2, jjq = rem & 3;
        float4 v = *(const float4*)(Wh + (size_t)k * ZDIM + gate * 512 + j0 + jjq * 4);
        int n = gate * 16 + jjq * 4;
        Bs[k][n + 0] = tf32cvt(v.x);
        Bs[k][n + 1] = tf32cvt(v.y);
        Bs[k][n + 2] = tf32cvt(v.z);
        Bs[k][n + 3] = tf32cvt(v.w);
    }
    __syncthreads();

    // cell state: 4 items/thread (item = tid + it*256 -> row item>>4, col item&15)
    float c_reg[4] = {0.0f, 0.0f, 0.0f, 0.0f};

    // this thread's barrier-poll slot (threads 0..31 poll own group's CTAs)
    const unsigned* my_flag = &g_arrive[((rg << 5) + (tid & 31)) * 8];

    // group staging map: warp wq stages rows wq*16 + (lane>>4) + 2i, i=0..7;
    // 16 float4 per row cover the 64-k chunk (lane&15 -> float4 index)
    const int sr = wq * 16 + (lane >> 4);
    const int sq = lane & 15;
    const int barid = 1 + grp;

    unsigned nxt_rdy = 0;   // tid0: prefetched g_ready[t] from previous step

    for (int t = 0; t < SEQ; t++) {
        // ---- merged top-of-step waits: xz[t] + h flags, ONE sync ----
        if (tid == 0 && nxt_rdy < 16u) {
            while (ld_acq(&g_ready[t]) < 16u) { __nanosleep(16); }
        }
        if (t > 0 && tid < 32) {
            while (ld_acq(my_flag) < (unsigned)t) { __nanosleep(16); }
        }
        __syncthreads();

        // prefetch next step's xz flag (consumed a full step later)
        if (tid == 0) nxt_rdy = (t + 1 < SEQ) ? ld_acq(&g_ready[t + 1]) : 0u;

        // ---- issue xf LDGs (consumed only in gates; latency rides under GEMM) ----
        float xf[16];
        {
            const float* xz = g_xz + (size_t)t * BATCH * ZDIM;
            #pragma unroll
            for (int it = 0; it < 4; it++) {
                int item = tid + it * 256;
                int b = item >> 4, jj = item & 15;
                const float* p = xz + (size_t)(row0 + b) * ZDIM + j0 + jj;
                xf[it * 4 + 0] = p[0];
                xf[it * 4 + 1] = p[512];
                xf[it * 4 + 2] = p[1024];
                xf[it * 4 + 3] = p[1536];
            }
        }

        if (t > 0) {
            // group's h base: k range [grp*256, +256)
            const float* hg = out + (size_t)(t - 1) * NBH + (size_t)row0 * HID + grp * 256;

            float acc[2][4][4];
            #pragma unroll
            for (int mt = 0; mt < 2; mt++)
                #pragma unroll
                for (int nt = 0; nt < 4; nt++)
                    #pragma unroll
                    for (int r = 0; r < 4; r++) acc[mt][nt][r] = 0.0f;

            // ---- prologue: stage chunk 0 -> bufA (group-local) ----
            #pragma unroll
            for (int i = 0; i < 8; i++) {
                int r = sr + i * 2;
                float4 v = *(const float4*)(hg + (size_t)r * HID + sq * 4);
                *(uint4*)&bufA[r][sq * 4] =
                    make_uint4(tf32cvt(v.x), tf32cvt(v.y), tf32cvt(v.z), tf32cvt(v.w));
            }
            bar_group(barid);

            // ---- 4 chunks of 64 k, pipelined, one group-barrier per chunk ----
            #pragma unroll
            for (int c = 0; c < 4; c++) {
                // stage chunk c+1 (LDG latency rides under the mma below)
                float4 stg[8];
                if (c < 3) {
                    const float* src = hg + (c + 1) * 64;
                    #pragma unroll
                    for (int i = 0; i < 8; i++) {
                        int r = sr + i * 2;
                        stg[i] = *(const float4*)(src + (size_t)r * HID + sq * 4);
                    }
                }

                // mma on chunk c (buffer holds exactly this group's 64 k)
                unsigned (*A)[AB_STR] = (c & 1) ? bufB : bufA;
                const int kb = grp * 256 + c * 64;     // k offset in Bs
                #pragma unroll
                for (int kk = 0; kk < 64; kk += 8) {
                    unsigned a[2][4], b[4][2];
                    #pragma unroll
                    for (int mt = 0; mt < 2; mt++) {
                        int mr = wm + mt * 16;
                        a[mt][0] = A[mr + gid][kk + tig];
                        a[mt][1] = A[mr + gid + 8][kk + tig];
                        a[mt][2] = A[mr + gid][kk + tig + 4];
                        a[mt][3] = A[mr + gid + 8][kk + tig + 4];
                    }
                    #pragma unroll
                    for (int nt = 0; nt < 4; nt++) {
                        int nc = wn + nt * 8;
                        b[nt][0] = Bs[kb + kk + tig][nc + gid];
                        b[nt][1] = Bs[kb + kk + tig + 4][nc + gid];
                    }
                    #pragma unroll
                    for (int mt = 0; mt < 2; mt++)
                        #pragma unroll
                        for (int nt = 0; nt < 4; nt++)
                            mma_tf32(acc[mt][nt], a[mt], b[nt]);
                }

                // store staged chunk c+1 into the other buffer
                // (its readers finished at the previous group-barrier)
                if (c < 3) {
                    unsigned (*D)[AB_STR] = (c & 1) ? bufA : bufB;
                    #pragma unroll
                    for (int i = 0; i < 8; i++) {
                        int r = sr + i * 2;
                        *(uint4*)&D[r][sq * 4] =
                            make_uint4(tf32cvt(stg[i].x), tf32cvt(stg[i].y),
                                       tf32cvt(stg[i].z), tf32cvt(stg[i].w));
                    }
                }
                bar_group(barid);
            }

            // ---- own K-group plane (overlays own bufA; last read chunk 2) ----
            {
                float (*Z)[65] = grp ? Zs1 : Zs0;
                #pragma unroll
                for (int mt = 0; mt < 2; mt++)
                    #pragma unroll
                    for (int nt = 0; nt < 4; nt++) {
                        int rr  = wm + mt * 16 + gid;
                        int col = wn + nt * 8 + 2 * tig;
                        Z[rr][col]         = acc[mt][nt][0];
                        Z[rr][col + 1]     = acc[mt][nt][1];
                        Z[rr + 8][col]     = acc[mt][nt][2];
                        Z[rr + 8][col + 1] = acc[mt][nt][3];
                    }
            }
            __syncthreads();   // join: both planes visible to all warps
        }

        // ---- gates + state update: 4 items per thread ----
        float* hout = out + (size_t)t * NBH;
        #pragma unroll
        for (int it = 0; it < 4; it++) {
            int item = tid + it * 256;
            int b = item >> 4, jj = item & 15;
            float zi, zf, zg, zo;
            if (t > 0) {
                zi = Zs0[b][jj]      + Zs1[b][jj];
                zf = Zs0[b][16 + jj] + Zs1[b][16 + jj];
                zg = Zs0[b][32 + jj] + Zs1[b][32 + jj];
                zo = Zs0[b][48 + jj] + Zs1[b][48 + jj];
            } else {
                zi = zf = zg = zo = 0.0f;
            }
            float ig = sigm_ap(zi + xf[it * 4 + 0]);
            float fg = sigm_ap(zf + xf[it * 4 + 1]);
            float gg = tanh_ap(zg + xf[it * 4 + 2]);
            float og = sigm_ap(zo + xf[it * 4 + 3]);
            float cn = fg * c_reg[it] + ig * gg;
            c_reg[it] = cn;
            hout[(size_t)(row0 + b) * HID + j0 + jj] = og * tanh_ap(cn);
        }

        // ---- arrive: bar makes all threads' h-writes happen-before tid0's
        //      release store (cumulative release; no MEMBAR.GPU needed) ----
        __syncthreads();
        if (tid == 0) st_rel(&g_arrive[cb * 8], (unsigned)(t + 1));
    }

    // ---- epilogue: append hT and cT ----
    {
        const float* hlast = out + (size_t)(SEQ - 1) * NBH;
        float* hT = out + (size_t)SEQ * NBH;
        float* cT = hT + NBH;
        #pragma unroll
        for (int it = 0; it < 4; it++) {
            int item = tid + it * 256;
            int b = item >> 4, jj = item & 15;
            size_t ci = (size_t)(row0 + b) * HID + j0 + jj;
            hT[ci] = hlast[ci];
            cT[ci] = c_reg[it];
        }
    }
}

// ---------------------------------------------------------------------------
extern "C" void kernel_launch(void* const* d_in, const int* in_sizes, int n_in,
                              void* d_out, int out_size) {
    const float* x    = (const float*)d_in[0];
    const float* W    = (const float*)d_in[1];
    const float* bias = (const float*)d_in[2];
    float* out = (float*)d_out;

    cudaFuncSetAttribute(lstm_persist_k,
                         cudaFuncAttributeMaxDynamicSharedMemorySize, SMEM_BYTES);

    reset_k<<<1, 1024>>>();
    lstm_persist_k<<<NREC + NPROD, 256, SMEM_BYTES>>>(out, x, W, bias);
}

// round 16
// speedup vs baseline: 1.1194x; 1.1194x over previous
#include <cuda_runtime.h>
#include <math.h>
#include <cstdint>

#define SEQ   1024
#define BATCH 128
#define EMB   512
#define HID   512
#define ZDIM  2048               // 4*HID
#define NBH   (BATCH * HID)      // 65536
#define NREC  64                 // recurrent CTAs (32 j-tiles x 2 row-groups)
#define NPROD 84                 // xz-producer CTAs
#define NTILE (SEQ * 16)         // xz tiles: 1024 timesteps x 16 n-tiles

// Scratch (allocation-free rule: __device__ globals)
__device__ float    g_xz[(size_t)SEQ * BATCH * ZDIM];   // 1 GiB: x@Wx + b
__device__ unsigned g_arrive[NREC * 8];                 // flag/CTA, 32B stride
__device__ unsigned g_ready[SEQ];                       // xz tiles done per t

// ---------------------------------------------------------------------------
// helpers
// ---------------------------------------------------------------------------
__device__ __forceinline__ unsigned tf32cvt(float x) {
    unsigned u;
    asm("cvt.rna.tf32.f32 %0, %1;" : "=r"(u) : "f"(x));
    return u;
}

__device__ __forceinline__ void mma_tf32(float* c, const unsigned* a, const unsigned* b) {
    asm volatile(
        "mma.sync.aligned.m16n8k8.row.col.f32.tf32.tf32.f32 "
        "{%0,%1,%2,%3}, {%4,%5,%6,%7}, {%8,%9}, {%0,%1,%2,%3};\n"
        : "+f"(c[0]), "+f"(c[1]), "+f"(c[2]), "+f"(c[3])
        : "r"(a[0]), "r"(a[1]), "r"(a[2]), "r"(a[3]), "r"(b[0]), "r"(b[1]));
}

__device__ __forceinline__ float tanh_ap(float x) {
    float y;
    asm("tanh.approx.f32 %0, %1;" : "=f"(y) : "f"(x));
    return y;
}
__device__ __forceinline__ float sigm_ap(float x) {
    return fmaf(tanh_ap(0.5f * x), 0.5f, 0.5f);
}

// acquire load / release store on global flags (no atomic-ALU serialization)
__device__ __forceinline__ unsigned ld_acq(const unsigned* p) {
    unsigned v;
    asm volatile("ld.global.acquire.gpu.u32 %0, [%1];" : "=r"(v) : "l"(p) : "memory");
    return v;
}
__device__ __forceinline__ void st_rel(unsigned* p, unsigned v) {
    asm volatile("st.global.release.gpu.u32 [%0], %1;" :: "l"(p), "r"(v) : "memory");
}

// named barrier: one per K-group (ids 1,2; id 0 left for __syncthreads)
__device__ __forceinline__ void bar_group(int id) {
    asm volatile("bar.sync %0, %1;" :: "r"(id), "r"(128) : "memory");
}

// ---------------------------------------------------------------------------
// reset (graph node 1): flags -> deterministic replays
// ---------------------------------------------------------------------------
__global__ void reset_k() {
    int i = threadIdx.x;
    if (i < SEQ) g_ready[i] = 0;
    if (i < NREC * 8) g_arrive[i] = 0;
}

// ---------------------------------------------------------------------------
// Dynamic smem layout (word offsets), recurrent-CTA view:
//   Bs  [512][72]      : Wh slice, gate-gathered (cached all steps) 147456 B
//   grp0: bufA/bufB [64][68] : 64-k chunks, double buffer           2x17408 B
//   grp1: bufA/bufB [64][68]                                        2x17408 B
//   Zs0 [64][65] overlays grp0 bufA; Zs1 [64][65] overlays grp1 bufA
// Producer-CTA view (overlay at word 0): Asp[128][17] | Bsp[16][136]
//
// Conflict math: Bs stride 72 (72%32=8 -> bank 8*tig+gid: distinct);
//                buf stride 68 (68%32=4 -> bank 4*gid+tig: distinct).
// ---------------------------------------------------------------------------
#define BS_STR  72
#define AB_STR  68
#define AB_WORDS (64 * AB_STR)               // 4352
#define SM_AS   (512 * BS_STR)               // 36864
#define SMEM_WORDS (SM_AS + 4 * AB_WORDS)    // 54272
#define SMEM_BYTES (SMEM_WORDS * 4)          // 217088 <= 232448 max

// ---------------------------------------------------------------------------
// Producer role: compute g_xz tiles (128 rows = one timestep, 128 cols),
// publish g_ready[t]. Verified R3/R5 body, 256 threads.
// ---------------------------------------------------------------------------
__device__ void xz_producer(const float* __restrict__ X,
                            const float* __restrict__ W,
                            const float* __restrict__ bias,
                            unsigned* smw, int pid) {
    unsigned (*As)[17]  = (unsigned(*)[17])smw;
    unsigned (*Bs)[136] = (unsigned(*)[136])(smw + 128 * 17);

    const int tid  = threadIdx.x;
    const int lane = tid & 31;
    const int w    = tid >> 5;
    const int wm = (w & 1) * 64;
    const int wn = (w >> 1) * 32;
    const int gid = lane >> 2;
    const int tig = lane & 3;

    for (int idx = pid; idx < NTILE; idx += NPROD) {
        const int t  = idx >> 4;
        const int bn = idx & 15;

        float acc[4][4][4];
        #pragma unroll
        for (int mt = 0; mt < 4; mt++)
            #pragma unroll
            for (int nt = 0; nt < 4; nt++)
                #pragma unroll
                for (int r = 0; r < 4; r++) acc[mt][nt][r] = 0.0f;

        const float* Ag = X + (size_t)t * 128 * EMB;
        const float* Bg = W + (size_t)bn * 128;

        for (int k0 = 0; k0 < EMB; k0 += 16) {
            #pragma unroll
            for (int i = 0; i < 2; i++) {
                int id2 = tid + i * 256;
                int r = id2 >> 2, c4 = id2 & 3;
                float4 v = *(const float4*)(Ag + (size_t)r * EMB + k0 + c4 * 4);
                As[r][c4 * 4 + 0] = tf32cvt(v.x);
                As[r][c4 * 4 + 1] = tf32cvt(v.y);
                As[r][c4 * 4 + 2] = tf32cvt(v.z);
                As[r][c4 * 4 + 3] = tf32cvt(v.w);
            }
            #pragma unroll
            for (int i = 0; i < 2; i++) {
                int id2 = tid + i * 256;
                int r = id2 >> 5, c4 = id2 & 31;
                float4 v = *(const float4*)(Bg + (size_t)(k0 + r) * ZDIM + c4 * 4);
                Bs[r][c4 * 4 + 0] = tf32cvt(v.x);
                Bs[r][c4 * 4 + 1] = tf32cvt(v.y);
                Bs[r][c4 * 4 + 2] = tf32cvt(v.z);
                Bs[r][c4 * 4 + 3] = tf32cvt(v.w);
            }
            __syncthreads();

            #pragma unroll
            for (int kk = 0; kk < 16; kk += 8) {
                unsigned a[4][4], b[4][2];
                #pragma unroll
                for (int mt = 0; mt < 4; mt++) {
                    int mr = wm + mt * 16;
                    a[mt][0] = As[mr + gid][kk + tig];
                    a[mt][1] = As[mr + gid + 8][kk + tig];
                    a[mt][2] = As[mr + gid][kk + tig + 4];
                    a[mt][3] = As[mr + gid + 8][kk + tig + 4];
                }
                #pragma unroll
                for (int nt = 0; nt < 4; nt++) {
                    int nc = wn + nt * 8;
                    b[nt][0] = Bs[kk + tig][nc + gid];
                    b[nt][1] = Bs[kk + tig + 4][nc + gid];
                }
                #pragma unroll
                for (int mt = 0; mt < 4; mt++)
                    #pragma unroll
                    for (int nt = 0; nt < 4; nt++)
                        mma_tf32(acc[mt][nt], a[mt], b[nt]);
            }
            __syncthreads();
        }

        #pragma unroll
        for (int mt = 0; mt < 4; mt++) {
            #pragma unroll
            for (int nt = 0; nt < 4; nt++) {
                int grow = t * 128 + wm + mt * 16 + gid;
                int gcol = bn * 128 + wn + nt * 8 + 2 * tig;
                float b0 = bias[gcol], b1 = bias[gcol + 1];
                float* p0 = g_xz + (size_t)grow * ZDIM + gcol;
                p0[0] = acc[mt][nt][0] + b0;
                p0[1] = acc[mt][nt][1] + b1;
                float* p1 = g_xz + (size_t)(grow + 8) * ZDIM + gcol;
                p1[0] = acc[mt][nt][2] + b0;
                p1[1] = acc[mt][nt][3] + b1;
            }
        }

        __threadfence();          // producer keeps the conservative fence
        __syncthreads();
        if (tid == 0) atomicAdd(&g_ready[t], 1u);   // 16 contributors: RMW needed
        __syncthreads();
    }
}

// ---------------------------------------------------------------------------
// Persistent kernel: 148 CTAs x 256 threads, one wave.
//   blockIdx.x <  64 : recurrent role (8 warps)
//   blockIdx.x >= 64 : xz-producer role
//
// Recurrent GEMM per step: z[64 x 64] = h_prev[64 x 512] @ WhSlice[512 x 64].
// R14 structure (proven champion), byte-identical EXCEPT one delta:
//   - the __threadfence() before the arrive is removed: the preceding
//     __syncthreads() makes all threads' h-STGs happen-before tid0's
//     st.release.gpu (cumulative release — coop-groups grid-sync pattern),
//     so MEMBAR.GPU on the per-step critical chain is redundant.
// Two decoupled 4-warp pipelines (group g = w>>2 owns K [g*256,+256) as 4
// chunks of 64 k, own double buffer + named barrier); R12 chunk pipeline;
// atomic-free 2-plane reduce; distributed flag barrier per row group.
// ---------------------------------------------------------------------------
__global__ __launch_bounds__(256, 1) void lstm_persist_k(float* __restrict__ out,
                                                         const float* __restrict__ X,
                                                         const float* __restrict__ W,
                                                         const float* __restrict__ bias) {
    extern __shared__ unsigned smw[];
    const int tid = threadIdx.x;

    if (blockIdx.x >= NREC) {
        xz_producer(X, W, bias, smw, blockIdx.x - NREC);
        return;
    }

    unsigned (*Bs)[BS_STR] = (unsigned(*)[BS_STR])smw;
    float    (*Zs0)[65]    = (float(*)[65])(smw + SM_AS);                // grp0 bufA
    float    (*Zs1)[65]    = (float(*)[65])(smw + SM_AS + 2 * AB_WORDS); // grp1 bufA

    const int cb   = blockIdx.x;
    const int j0   = (cb & 31) * 16;      // hidden-col tile
    const int rg   = cb >> 5;             // row group 0/1
    const int row0 = rg * 64;             // batch-row tile
    const int lane = tid & 31;
    const int w    = tid >> 5;            // 0..7
    const int grp  = w >> 2;              // K-group 0/1 (contiguous 256 k)
    const int wq   = w & 3;               // warp within group
    const int wm   = (wq & 1) * 32;
    const int wn   = (wq >> 1) * 32;
    const int gid  = lane >> 2;
    const int tig  = lane & 3;

    // group-local double buffer
    unsigned (*bufA)[AB_STR] = (unsigned(*)[AB_STR])(smw + SM_AS + grp * 2 * AB_WORDS);
    unsigned (*bufB)[AB_STR] = (unsigned(*)[AB_STR])(smw + SM_AS + grp * 2 * AB_WORDS + AB_WORDS);

    // ---- one-time: cache Wh slice (gate-gathered, tf32) in smem ----
    // Bs[k][n], n = gate*16 + jj  ->  Wh[k][gate*512 + j0 + jj]
    const float* Wh = W + (size_t)EMB * ZDIM;
    #pragma unroll 4
    for (int i = 0; i < 32; i++) {
        int idx  = tid + i * 256;            // 8192 float4s
        int k    = idx >> 4;
        int rem  = idx & 15;
        int gate = rem >> 2, jjq = rem & 3;
        float4 v = *(const float4*)(Wh + (size_t)k * ZDIM + gate * 512 + j0 + jjq * 4);
        int n = gate * 16 + jjq * 4;
        Bs[k][n + 0] = tf32cvt(v.x);
        Bs[k][n + 1] = tf32cvt(v.y);
        Bs[k][n + 2] = tf32cvt(v.z);
        Bs[k][n + 3] = tf32cvt(v.w);
    }
    __syncthreads();

    // cell state: 4 items/thread (item = tid + it*256 -> row item>>4, col item&15)
    float c_reg[4] = {0.0f, 0.0f, 0.0f, 0.0f};

    // this thread's barrier-poll slot (threads 0..31 poll own group's CTAs)
    const unsigned* my_flag = &g_arrive[((rg << 5) + (tid & 31)) * 8];

    // group staging map: warp wq stages rows wq*16 + (lane>>4) + 2i, i=0..7;
    // 16 float4 per row cover the 64-k chunk (lane&15 -> float4 index)
    const int sr = wq * 16 + (lane >> 4);
    const int sq = lane & 15;
    const int barid = 1 + grp;

    for (int t = 0; t < SEQ; t++) {
        // ---- wait for xz[t] (acquire-load poll, thread 0 only) ----
        if (tid == 0) {
            while (ld_acq(&g_ready[t]) < 16u) { __nanosleep(16); }
        }
        __syncthreads();

        // ---- issue xf LDGs early (consumed only in gates) ----
        float xf[16];
        {
            const float* xz = g_xz + (size_t)t * BATCH * ZDIM;
            #pragma unroll
            for (int it = 0; it < 4; it++) {
                int item = tid + it * 256;
                int b = item >> 4, jj = item & 15;
                const float* p = xz + (size_t)(row0 + b) * ZDIM + j0 + jj;
                xf[it * 4 + 0] = p[0];
                xf[it * 4 + 1] = p[512];
                xf[it * 4 + 2] = p[1024];
                xf[it * 4 + 3] = p[1536];
            }
        }

        if (t > 0) {
            // ---- wait for own row group's step-(t-1) h writes ----
            if (tid < 32) {
                while (ld_acq(my_flag) < (unsigned)t) { __nanosleep(16); }
            }
            __syncthreads();

            // group's h base: k range [grp*256, +256)
            const float* hg = out + (size_t)(t - 1) * NBH + (size_t)row0 * HID + grp * 256;

            float acc[2][4][4];
            #pragma unroll
            for (int mt = 0; mt < 2; mt++)
                #pragma unroll
                for (int nt = 0; nt < 4; nt++)
                    #pragma unroll
                    for (int r = 0; r < 4; r++) acc[mt][nt][r] = 0.0f;

            // ---- prologue: stage chunk 0 -> bufA (group-local) ----
            #pragma unroll
            for (int i = 0; i < 8; i++) {
                int r = sr + i * 2;
                float4 v = *(const float4*)(hg + (size_t)r * HID + sq * 4);
                *(uint4*)&bufA[r][sq * 4] =
                    make_uint4(tf32cvt(v.x), tf32cvt(v.y), tf32cvt(v.z), tf32cvt(v.w));
            }
            bar_group(barid);

            // ---- 4 chunks of 64 k, pipelined, one group-barrier per chunk ----
            #pragma unroll
            for (int c = 0; c < 4; c++) {
                // stage chunk c+1 (LDG latency rides under the mma below)
                float4 stg[8];
                if (c < 3) {
                    const float* src = hg + (c + 1) * 64;
                    #pragma unroll
                    for (int i = 0; i < 8; i++) {
                        int r = sr + i * 2;
                        stg[i] = *(const float4*)(src + (size_t)r * HID + sq * 4);
                    }
                }

                // mma on chunk c (buffer holds exactly this group's 64 k)
                unsigned (*A)[AB_STR] = (c & 1) ? bufB : bufA;
                const int kb = grp * 256 + c * 64;     // k offset in Bs
                #pragma unroll
                for (int kk = 0; kk < 64; kk += 8) {
                    unsigned a[2][4], b[4][2];
                    #pragma unroll
                    for (int mt = 0; mt < 2; mt++) {
                        int mr = wm + mt * 16;
                        a[mt][0] = A[mr + gid][kk + tig];
                        a[mt][1] = A[mr + gid + 8][kk + tig];
                        a[mt][2] = A[mr + gid][kk + tig + 4];
                        a[mt][3] = A[mr + gid + 8][kk + tig + 4];
                    }
                    #pragma unroll
                    for (int nt = 0; nt < 4; nt++) {
                        int nc = wn + nt * 8;
                        b[nt][0] = Bs[kb + kk + tig][nc + gid];
                        b[nt][1] = Bs[kb + kk + tig + 4][nc + gid];
                    }
                    #pragma unroll
                    for (int mt = 0; mt < 2; mt++)
                        #pragma unroll
                        for (int nt = 0; nt < 4; nt++)
                            mma_tf32(acc[mt][nt], a[mt], b[nt]);
                }

                // store staged chunk c+1 into the other buffer
                // (its readers finished at the previous group-barrier)
                if (c < 3) {
                    unsigned (*D)[AB_STR] = (c & 1) ? bufA : bufB;
                    #pragma unroll
                    for (int i = 0; i < 8; i++) {
                        int r = sr + i * 2;
                        *(uint4*)&D[r][sq * 4] =
                            make_uint4(tf32cvt(stg[i].x), tf32cvt(stg[i].y),
                                       tf32cvt(stg[i].z), tf32cvt(stg[i].w));
                    }
                }
                bar_group(barid);
            }

            // ---- own K-group plane (overlays own bufA; last read chunk 2) ----
            {
                float (*Z)[65] = grp ? Zs1 : Zs0;
                #pragma unroll
                for (int mt = 0; mt < 2; mt++)
                    #pragma unroll
                    for (int nt = 0; nt < 4; nt++) {
                        int rr  = wm + mt * 16 + gid;
                        int col = wn + nt * 8 + 2 * tig;
                        Z[rr][col]         = acc[mt][nt][0];
                        Z[rr][col + 1]     = acc[mt][nt][1];
                        Z[rr + 8][col]     = acc[mt][nt][2];
                        Z[rr + 8][col + 1] = acc[mt][nt][3];
                    }
            }
            __syncthreads();   // join: both planes visible to all warps
        }

        // ---- gates + state update: 4 items per thread ----
        float* hout = out + (size_t)t * NBH;
        #pragma unroll
        for (int it = 0; it < 4; it++) {
            int item = tid + it * 256;
            int b = item >> 4, jj = item & 15;
            float zi, zf, zg, zo;
            if (t > 0) {
                zi = Zs0[b][jj]      + Zs1[b][jj];
                zf = Zs0[b][16 + jj] + Zs1[b][16 + jj];
                zg = Zs0[b][32 + jj] + Zs1[b][32 + jj];
                zo = Zs0[b][48 + jj] + Zs1[b][48 + jj];
            } else {
                zi = zf = zg = zo = 0.0f;
            }
            float ig = sigm_ap(zi + xf[it * 4 + 0]);
            float fg = sigm_ap(zf + xf[it * 4 + 1]);
            float gg = tanh_ap(zg + xf[it * 4 + 2]);
            float og = sigm_ap(zo + xf[it * 4 + 3]);
            float cn = fg * c_reg[it] + ig * gg;
            c_reg[it] = cn;
            hout[(size_t)(row0 + b) * HID + j0 + jj] = og * tanh_ap(cn);
        }

        // ---- arrive: bar makes all threads' h-writes happen-before tid0's
        //      release store (cumulative release; no MEMBAR.GPU needed) ----
        __syncthreads();
        if (tid == 0) st_rel(&g_arrive[cb * 8], (unsigned)(t + 1));
    }

    // ---- epilogue: append hT and cT ----
    {
        const float* hlast = out + (size_t)(SEQ - 1) * NBH;
        float* hT = out + (size_t)SEQ * NBH;
        float* cT = hT + NBH;
        #pragma unroll
        for (int it = 0; it < 4; it++) {
            int item = tid + it * 256;
            int b = item >> 4, jj = item & 15;
            size_t ci = (size_t)(row0 + b) * HID + j0 + jj;
            hT[ci] = hlast[ci];
            cT[ci] = c_reg[it];
        }
    }
}

// ---------------------------------------------------------------------------
extern "C" void kernel_launch(void* const* d_in, const int* in_sizes, int n_in,
                              void* d_out, int out_size) {
    const float* x    = (const float*)d_in[0];
    const float* W    = (const float*)d_in[1];
    const float* bias = (const float*)d_in[2];
    float* out = (float*)d_out;

    cudaFuncSetAttribute(lstm_persist_k,
                         cudaFuncAttributeMaxDynamicSharedMemorySize, SMEM_BYTES);

    reset_k<<<1, 1024>>>();
    lstm_persist_k<<<NREC + NPROD, 256, SMEM_BYTES>>>(out, x, W, bias);
}